// round 2
// baseline (speedup 1.0000x reference)
#include <cuda_runtime.h>
#include <cuda_bf16.h>
#include <cstdint>

// Problem constants
#define Bsz 2
#define Lseq 1024
#define DIN 512
#define DM 1024
#define NLAYER 4
#define Eexp 2048
#define Nst 16
#define Rrank 64
#define Kconv 4
#define Mrows (Bsz*Lseq)   // 2048

// ---------------- scratch (device globals; no allocation allowed) ----------
__device__ float g_h   [Mrows*DM];        // residual stream
__device__ float g_hn  [Mrows*DM];        // layernorm output
__device__ float g_xz  [Mrows*2*Eexp];    // inproj output (xm_pre | zg)
__device__ float g_xm  [Mrows*Eexp];      // conv+silu output (u)
__device__ float g_xdbl[Mrows*96];        // x_dbl (dt_r | B | C), row stride 96
__device__ float g_dt  [Mrows*Eexp];      // softplus(dt)
__device__ float g_yg  [Mrows*Eexp];      // gated scan output

// ---------------- generic NT SGEMM: C[m,n] = sum_k A[m,k]*W[n,k] ----------
// EPI: 0 = store, 1 = store + bias[n], 2 = softplus(acc + bias[n]), 3 = C += acc
#define BM 128
#define BN 128
#define BKs 16
#define TM 8
#define TN 8

template<int EPI>
__global__ void __launch_bounds__(256)
sgemm_nt(const float* __restrict__ A, int lda,
         const float* __restrict__ W, int ldw,
         float* __restrict__ C, int ldc,
         int M, int N, int K, const float* __restrict__ bias)
{
    __shared__ float As[BKs][BM];
    __shared__ float Ws[BKs][BN];

    const int tid = threadIdx.x;
    const int bm = blockIdx.y * BM;
    const int bn = blockIdx.x * BN;
    const int tx = tid & 15;          // 0..15  -> N direction
    const int ty = tid >> 4;          // 0..15  -> M direction

    const int lr = tid >> 2;          // 0..63 load row
    const int lc = (tid & 3) * 4;     // 0,4,8,12 load col (floats)

    float acc[TM][TN];
    #pragma unroll
    for (int i = 0; i < TM; i++)
        #pragma unroll
        for (int j = 0; j < TN; j++) acc[i][j] = 0.f;

    for (int k0 = 0; k0 < K; k0 += BKs) {
        // A tile (M always multiple of 128 here -> no M guard)
        #pragma unroll
        for (int h = 0; h < 2; h++) {
            int r = lr + h * 64;
            float4 v = *(const float4*)(A + (size_t)(bm + r) * lda + k0 + lc);
            As[lc + 0][r] = v.x; As[lc + 1][r] = v.y;
            As[lc + 2][r] = v.z; As[lc + 3][r] = v.w;
        }
        // W tile (guard N: xproj has N=96)
        #pragma unroll
        for (int h = 0; h < 2; h++) {
            int r = lr + h * 64;
            int n = bn + r;
            float4 v = make_float4(0.f, 0.f, 0.f, 0.f);
            if (n < N) v = *(const float4*)(W + (size_t)n * ldw + k0 + lc);
            Ws[lc + 0][r] = v.x; Ws[lc + 1][r] = v.y;
            Ws[lc + 2][r] = v.z; Ws[lc + 3][r] = v.w;
        }
        __syncthreads();

        #pragma unroll
        for (int k = 0; k < BKs; k++) {
            float a[TM], b[TN];
            #pragma unroll
            for (int i = 0; i < TM; i++) a[i] = As[k][ty * TM + i];
            #pragma unroll
            for (int j = 0; j < TN; j++) b[j] = Ws[k][tx * TN + j];
            #pragma unroll
            for (int i = 0; i < TM; i++)
                #pragma unroll
                for (int j = 0; j < TN; j++)
                    acc[i][j] = fmaf(a[i], b[j], acc[i][j]);
        }
        __syncthreads();
    }

    #pragma unroll
    for (int i = 0; i < TM; i++) {
        int m = bm + ty * TM + i;
        #pragma unroll
        for (int j = 0; j < TN; j++) {
            int n = bn + tx * TN + j;
            if (n < N) {
                float v = acc[i][j];
                float* cp = C + (size_t)m * ldc + n;
                if (EPI == 0) {
                    *cp = v;
                } else if (EPI == 1) {
                    *cp = v + bias[n];
                } else if (EPI == 2) {
                    float s = v + bias[n];
                    // softplus, numerically stable
                    *cp = fmaxf(s, 0.f) + log1pf(__expf(-fabsf(s)));
                } else { // 3: residual accumulate
                    *cp += v;
                }
            }
        }
    }
}

// ---------------- layernorm over rows of length DM=1024 -------------------
__global__ void __launch_bounds__(256)
ln_kernel(const float* __restrict__ x, const float* __restrict__ w,
          const float* __restrict__ b, float* __restrict__ y)
{
    const int row = blockIdx.x;
    const float* xr = x + (size_t)row * DM;
    float* yr = y + (size_t)row * DM;
    const int tid = threadIdx.x;

    float vals[4];
    float s = 0.f, ss = 0.f;
    #pragma unroll
    for (int i = 0; i < 4; i++) {
        float v = xr[tid + i * 256];
        vals[i] = v;
        s += v; ss += v * v;
    }
    // warp reduce
    #pragma unroll
    for (int o = 16; o > 0; o >>= 1) {
        s  += __shfl_xor_sync(0xffffffffu, s, o);
        ss += __shfl_xor_sync(0xffffffffu, ss, o);
    }
    __shared__ float sh[16], shh[16];
    int wid = tid >> 5, ln = tid & 31;
    if (ln == 0) { sh[wid] = s; shh[wid] = ss; }
    __syncthreads();
    if (wid == 0) {
        float a = (ln < 8) ? sh[ln] : 0.f;
        float c = (ln < 8) ? shh[ln] : 0.f;
        #pragma unroll
        for (int o = 4; o > 0; o >>= 1) {
            a += __shfl_xor_sync(0xffffffffu, a, o);
            c += __shfl_xor_sync(0xffffffffu, c, o);
        }
        if (ln == 0) { sh[0] = a; shh[0] = c; }
    }
    __syncthreads();
    float mean = sh[0] * (1.f / DM);
    float var  = shh[0] * (1.f / DM) - mean * mean;
    float rstd = rsqrtf(var + 1e-5f);
    #pragma unroll
    for (int i = 0; i < 4; i++) {
        int c = tid + i * 256;
        yr[c] = (vals[i] - mean) * rstd * w[c] + b[c];
    }
}

// -------- depthwise causal conv (K=4) + bias + silu, from xz[:, :E] -------
// out[b,t,e] = silu( cb[e] + sum_k cw[e,k]*xz[b, t-3+k, e] )
__global__ void __launch_bounds__(256)
conv_silu_kernel(const float* __restrict__ xz, const float* __restrict__ cw,
                 const float* __restrict__ cb, float* __restrict__ xm)
{
    const int e  = blockIdx.x * 256 + threadIdx.x;   // 0..2047
    const int t0 = blockIdx.y * 8;                   // 8 timesteps per thread
    const int b  = blockIdx.z;
    const float4 w = *(const float4*)(cw + e * 4);
    const float bias = cb[e];
    const float* base = xz + (size_t)b * Lseq * (2 * Eexp) + e;

    float v[11];
    #pragma unroll
    for (int i = 0; i < 11; i++) {
        int t = t0 - 3 + i;
        v[i] = (t >= 0) ? base[(size_t)t * (2 * Eexp)] : 0.f;
    }
    #pragma unroll
    for (int j = 0; j < 8; j++) {
        float sacc = bias;
        sacc = fmaf(w.x, v[j],     sacc);
        sacc = fmaf(w.y, v[j + 1], sacc);
        sacc = fmaf(w.z, v[j + 2], sacc);
        sacc = fmaf(w.w, v[j + 3], sacc);
        float sv = sacc / (1.f + __expf(-sacc));      // silu
        xm[((size_t)b * Lseq + t0 + j) * Eexp + e] = sv;
    }
}

// ---------------- selective scan + gating ---------------------------------
// 16 lanes per channel (one per state n); h in register; butterfly reduce.
__global__ void __launch_bounds__(256)
scan_kernel(const float* __restrict__ u,    const float* __restrict__ dt,
            const float* __restrict__ xdbl, const float* __restrict__ Alog,
            const float* __restrict__ Dp,   const float* __restrict__ xz,
            float* __restrict__ yg)
{
    const int tid = threadIdx.x;
    const int grp = tid >> 4;           // 0..15 channel within block
    const int n   = tid & 15;           // state index
    const int blk = blockIdx.x;         // 0..255
    const int b   = blk >> 7;
    const int e   = ((blk & 127) << 4) + grp;

    const float A = -__expf(Alog[e * Nst + n]);
    const float D = Dp[e];
    float h = 0.f;
    const size_t rbase = (size_t)b * Lseq;

    // prefetch t = 0
    float dts = dt[rbase * Eexp + e];
    float us  = u [rbase * Eexp + e];
    float Bn  = xdbl[rbase * 96 + Rrank + n];
    float Cn  = xdbl[rbase * 96 + Rrank + Nst + n];

    for (int t = 0; t < Lseq; t++) {
        float dts_c = dts, us_c = us, Bn_c = Bn, Cn_c = Cn;
        if (t + 1 < Lseq) {
            size_t r = rbase + t + 1;
            dts = dt[r * Eexp + e];
            us  = u [r * Eexp + e];
            Bn  = xdbl[r * 96 + Rrank + n];
            Cn  = xdbl[r * 96 + Rrank + Nst + n];
        }
        float dA = __expf(dts_c * A);
        h = fmaf(dA, h, (dts_c * us_c) * Bn_c);
        float p = h * Cn_c;
        p += __shfl_xor_sync(0xffffffffu, p, 1);
        p += __shfl_xor_sync(0xffffffffu, p, 2);
        p += __shfl_xor_sync(0xffffffffu, p, 4);
        p += __shfl_xor_sync(0xffffffffu, p, 8);
        if (n == 0) {
            size_t r = rbase + t;
            float zv = xz[r * (2 * Eexp) + Eexp + e];
            float yv = fmaf(us_c, D, p);
            yg[r * Eexp + e] = yv * (zv / (1.f + __expf(-zv)));
        }
    }
}

// ---------------- host driver ---------------------------------------------
extern "C" void kernel_launch(void* const* d_in, const int* in_sizes, int n_in,
                              void* d_out, int out_size)
{
    const float* x        = (const float*)d_in[0];
    // d_in[1] = z (unused by reference)
    const float* ip_w     = (const float*)d_in[2];
    const float* ip_b     = (const float*)d_in[3];
    const float* ln_w     = (const float*)d_in[4];
    const float* ln_b     = (const float*)d_in[5];
    const float* inproj_w = (const float*)d_in[6];
    const float* conv_w   = (const float*)d_in[7];
    const float* conv_b   = (const float*)d_in[8];
    const float* xproj_w  = (const float*)d_in[9];
    const float* dtproj_w = (const float*)d_in[10];
    const float* dtproj_b = (const float*)d_in[11];
    const float* A_log    = (const float*)d_in[12];
    const float* Dp       = (const float*)d_in[13];
    const float* outproj_w= (const float*)d_in[14];
    const float* fnorm_w  = (const float*)d_in[15];
    const float* fnorm_b  = (const float*)d_in[16];
    const float* op_w     = (const float*)d_in[17];
    const float* op_b     = (const float*)d_in[18];
    float* out = (float*)d_out;

    float *h, *hn, *xz, *xm, *xdbl, *dtb, *yg;
    cudaGetSymbolAddress((void**)&h,    g_h);
    cudaGetSymbolAddress((void**)&hn,   g_hn);
    cudaGetSymbolAddress((void**)&xz,   g_xz);
    cudaGetSymbolAddress((void**)&xm,   g_xm);
    cudaGetSymbolAddress((void**)&xdbl, g_xdbl);
    cudaGetSymbolAddress((void**)&dtb,  g_dt);
    cudaGetSymbolAddress((void**)&yg,   g_yg);

    // input projection: h = x @ ip_w^T + ip_b   (2048 x 1024 x 512)
    sgemm_nt<1><<<dim3(DM / BN, Mrows / BM), 256>>>(
        x, DIN, ip_w, DIN, h, DM, Mrows, DM, DIN, ip_b);

    for (int l = 0; l < NLAYER; l++) {
        // hn = LN(h)
        ln_kernel<<<Mrows, 256>>>(h, ln_w + l * DM, ln_b + l * DM, hn);

        // xz = hn @ inproj^T   (2048 x 4096 x 1024)
        sgemm_nt<0><<<dim3(2 * Eexp / BN, Mrows / BM), 256>>>(
            hn, DM, inproj_w + (size_t)l * 2 * Eexp * DM, DM,
            xz, 2 * Eexp, Mrows, 2 * Eexp, DM, nullptr);

        // xm = silu(causal depthwise conv(xz[:, :E]))
        conv_silu_kernel<<<dim3(Eexp / 256, Lseq / 8, Bsz), 256>>>(
            xz, conv_w + l * Eexp * Kconv, conv_b + l * Eexp, xm);

        // x_dbl = xm @ xproj^T   (2048 x 96 x 2048)
        sgemm_nt<0><<<dim3(1, Mrows / BM), 256>>>(
            xm, Eexp, xproj_w + (size_t)l * 96 * Eexp, Eexp,
            xdbl, 96, Mrows, 96, Eexp, nullptr);

        // dt = softplus(x_dbl[:, :R] @ dtproj^T + dtproj_b)  (2048 x 2048 x 64)
        sgemm_nt<2><<<dim3(Eexp / BN, Mrows / BM), 256>>>(
            xdbl, 96, dtproj_w + (size_t)l * Eexp * Rrank, Rrank,
            dtb, Eexp, Mrows, Eexp, Rrank, dtproj_b + l * Eexp);

        // selective scan + D skip + silu(zg) gating -> yg
        scan_kernel<<<256, 256>>>(
            xm, dtb, xdbl, A_log + l * Eexp * Nst, Dp + l * Eexp, xz, yg);

        // h += yg @ outproj^T   (2048 x 1024 x 2048)
        sgemm_nt<3><<<dim3(DM / BN, Mrows / BM), 256>>>(
            yg, Eexp, outproj_w + (size_t)l * DM * Eexp, Eexp,
            h, DM, Mrows, DM, Eexp, nullptr);
    }

    // final LN + output projection: out = LN(h) @ op_w^T + op_b (2048x512x1024)
    ln_kernel<<<Mrows, 256>>>(h, fnorm_w, fnorm_b, hn);
    sgemm_nt<1><<<dim3(DIN / BN, Mrows / BM), 256>>>(
        hn, DM, op_w, DM, out, DIN, Mrows, DIN, DM, op_b);
}

// round 3
// speedup vs baseline: 1.8867x; 1.8867x over previous
#include <cuda_runtime.h>
#include <cuda_bf16.h>
#include <cstdint>

// Problem constants
#define Bsz 2
#define Lseq 1024
#define DIN 512
#define DM 1024
#define NLAYER 4
#define Eexp 2048
#define Nst 16
#define Rrank 64
#define Kconv 4
#define Mrows (Bsz*Lseq)   // 2048

// ---------------- scratch (device globals; no allocation allowed) ----------
__device__ float g_h   [Mrows*DM];
__device__ float g_hn  [Mrows*DM];
__device__ float g_xz  [Mrows*2*Eexp];
__device__ float g_xm  [Mrows*Eexp];
__device__ float g_xdbl[Mrows*96];
__device__ float g_dt  [Mrows*Eexp];
__device__ float g_yg  [Mrows*Eexp];

// =================== tf32 tensor-core NT GEMM ==============================
// C[m,n] = sum_k A[m,k] * W[n,k];  A row-major [M,K], W row-major [N,K]
// EPI: 0 = store, 1 = store+bias[n], 3 = C += acc
#define TBM 128
#define TBN 128
#define TBK 32
#define TROW 36              // padded row stride in floats (32 + 4)
#define TSTAGE (TBM*TROW)    // floats per tile per stage (4608)

__device__ __forceinline__ uint32_t smem_u32(const void* p) {
    return (uint32_t)__cvta_generic_to_shared(p);
}
__device__ __forceinline__ void cp_async16(uint32_t dst, const void* src, int src_bytes) {
    asm volatile("cp.async.cg.shared.global [%0], [%1], 16, %2;\n"
                 :: "r"(dst), "l"(src), "r"(src_bytes));
}
__device__ __forceinline__ void cp_commit() {
    asm volatile("cp.async.commit_group;\n");
}
template<int NPend>
__device__ __forceinline__ void cp_wait() {
    asm volatile("cp.async.wait_group %0;\n" :: "n"(NPend));
}
__device__ __forceinline__ void mma_tf32(float* d, const uint32_t* a, const uint32_t* b) {
    asm volatile(
        "mma.sync.aligned.m16n8k8.row.col.f32.tf32.tf32.f32 "
        "{%0,%1,%2,%3}, {%4,%5,%6,%7}, {%8,%9}, {%0,%1,%2,%3};\n"
        : "+f"(d[0]), "+f"(d[1]), "+f"(d[2]), "+f"(d[3])
        : "r"(a[0]), "r"(a[1]), "r"(a[2]), "r"(a[3]), "r"(b[0]), "r"(b[1]));
}

template<int EPI>
__global__ void __launch_bounds__(256, 2)
tgemm_nt(const float* __restrict__ A, int lda,
         const float* __restrict__ W, int ldw,
         float* __restrict__ C, int ldc,
         int M, int N, int K, const float* __restrict__ bias)
{
    extern __shared__ float sm[];
    float* As = sm;                 // [2][TBM][TROW]
    float* Ws = sm + 2 * TSTAGE;    // [2][TBN][TROW]

    const int tid  = threadIdx.x;
    const int bm   = blockIdx.y * TBM;
    const int bn   = blockIdx.x * TBN;
    const int warp = tid >> 5, lane = tid & 31;
    const int wm   = warp & 3;      // 0..3 -> 32-row band
    const int wn   = warp >> 2;     // 0..1 -> 64-col band
    const int gid  = lane >> 2, tig = lane & 3;

    float acc[2][8][4];
    #pragma unroll
    for (int i = 0; i < 2; i++)
        #pragma unroll
        for (int j = 0; j < 8; j++)
            #pragma unroll
            for (int q = 0; q < 4; q++) acc[i][j][q] = 0.f;

    // global->smem loaders: 1024 float4 per tile, 4 per thread
    const int lrow = tid >> 1;            // reused below differently
    (void)lrow;

    auto ldA = [&](int stage, int k0) {
        #pragma unroll
        for (int t = 0; t < 4; t++) {
            int idx = tid + t * 256;
            int r = idx >> 3, kc = (idx & 7) * 4;
            cp_async16(smem_u32(As + stage * TSTAGE + r * TROW + kc),
                       A + (size_t)(bm + r) * lda + k0 + kc, 16);
        }
    };
    auto ldW = [&](int stage, int k0) {
        #pragma unroll
        for (int t = 0; t < 4; t++) {
            int idx = tid + t * 256;
            int r = idx >> 3, kc = (idx & 7) * 4;
            int n = bn + r;
            int ok = (n < N);
            cp_async16(smem_u32(Ws + stage * TSTAGE + r * TROW + kc),
                       W + (size_t)(ok ? n : 0) * ldw + k0 + kc, ok ? 16 : 0);
        }
    };

    const int nk = K / TBK;
    ldA(0, 0); ldW(0, 0); cp_commit();

    for (int it = 0; it < nk; it++) {
        int stage = it & 1;
        if (it + 1 < nk) {
            ldA(stage ^ 1, (it + 1) * TBK);
            ldW(stage ^ 1, (it + 1) * TBK);
            cp_commit();
            cp_wait<1>();
        } else {
            cp_wait<0>();
        }
        __syncthreads();

        const uint32_t* Asu = (const uint32_t*)(As + stage * TSTAGE);
        const uint32_t* Wsu = (const uint32_t*)(Ws + stage * TSTAGE);

        #pragma unroll
        for (int kk = 0; kk < TBK; kk += 8) {
            uint32_t af[2][4];
            #pragma unroll
            for (int mt = 0; mt < 2; mt++) {
                int r = wm * 32 + mt * 16 + gid;
                const uint32_t* ap = Asu + r * TROW + kk + tig;
                af[mt][0] = ap[0];
                af[mt][1] = ap[8 * TROW];
                af[mt][2] = ap[4];
                af[mt][3] = ap[8 * TROW + 4];
            }
            uint32_t bf[8][2];
            #pragma unroll
            for (int nt = 0; nt < 8; nt++) {
                int n = wn * 64 + nt * 8 + gid;
                const uint32_t* bp = Wsu + n * TROW + kk + tig;
                bf[nt][0] = bp[0];
                bf[nt][1] = bp[4];
            }
            #pragma unroll
            for (int mt = 0; mt < 2; mt++)
                #pragma unroll
                for (int nt = 0; nt < 8; nt++)
                    mma_tf32(acc[mt][nt], af[mt], bf[nt]);
        }
        __syncthreads();
    }

    // epilogue
    #pragma unroll
    for (int mt = 0; mt < 2; mt++) {
        int r0 = bm + wm * 32 + mt * 16 + gid;
        #pragma unroll
        for (int nt = 0; nt < 8; nt++) {
            int col = bn + wn * 64 + nt * 8 + tig * 2;
            #pragma unroll
            for (int h = 0; h < 2; h++) {        // row gid / gid+8
                int m = r0 + h * 8;
                #pragma unroll
                for (int q = 0; q < 2; q++) {    // col, col+1
                    int n = col + q;
                    if (n < N) {
                        float v = acc[mt][nt][h * 2 + q];
                        float* cp = C + (size_t)m * ldc + n;
                        if (EPI == 0)      *cp = v;
                        else if (EPI == 1) *cp = v + bias[n];
                        else               *cp += v;   // EPI==3
                    }
                }
            }
        }
    }
}

// =================== fp32 SIMT GEMM (kept for dtproj) ======================
#define BM 128
#define BN 128
#define BKs 16
#define TM 8
#define TN 8

template<int EPI>   // 2 = softplus(acc + bias[n])
__global__ void __launch_bounds__(256)
sgemm_nt(const float* __restrict__ A, int lda,
         const float* __restrict__ W, int ldw,
         float* __restrict__ C, int ldc,
         int M, int N, int K, const float* __restrict__ bias)
{
    __shared__ float As[BKs][BM];
    __shared__ float Ws[BKs][BN];

    const int tid = threadIdx.x;
    const int bm = blockIdx.y * BM;
    const int bn = blockIdx.x * BN;
    const int tx = tid & 15;
    const int ty = tid >> 4;
    const int lr = tid >> 2;
    const int lc = (tid & 3) * 4;

    float acc[TM][TN];
    #pragma unroll
    for (int i = 0; i < TM; i++)
        #pragma unroll
        for (int j = 0; j < TN; j++) acc[i][j] = 0.f;

    for (int k0 = 0; k0 < K; k0 += BKs) {
        #pragma unroll
        for (int h = 0; h < 2; h++) {
            int r = lr + h * 64;
            float4 v = *(const float4*)(A + (size_t)(bm + r) * lda + k0 + lc);
            As[lc + 0][r] = v.x; As[lc + 1][r] = v.y;
            As[lc + 2][r] = v.z; As[lc + 3][r] = v.w;
        }
        #pragma unroll
        for (int h = 0; h < 2; h++) {
            int r = lr + h * 64;
            int n = bn + r;
            float4 v = make_float4(0.f, 0.f, 0.f, 0.f);
            if (n < N) v = *(const float4*)(W + (size_t)n * ldw + k0 + lc);
            Ws[lc + 0][r] = v.x; Ws[lc + 1][r] = v.y;
            Ws[lc + 2][r] = v.z; Ws[lc + 3][r] = v.w;
        }
        __syncthreads();

        #pragma unroll
        for (int k = 0; k < BKs; k++) {
            float a[TM], b[TN];
            #pragma unroll
            for (int i = 0; i < TM; i++) a[i] = As[k][ty * TM + i];
            #pragma unroll
            for (int j = 0; j < TN; j++) b[j] = Ws[k][tx * TN + j];
            #pragma unroll
            for (int i = 0; i < TM; i++)
                #pragma unroll
                for (int j = 0; j < TN; j++)
                    acc[i][j] = fmaf(a[i], b[j], acc[i][j]);
        }
        __syncthreads();
    }

    #pragma unroll
    for (int i = 0; i < TM; i++) {
        int m = bm + ty * TM + i;
        #pragma unroll
        for (int j = 0; j < TN; j++) {
            int n = bn + tx * TN + j;
            if (n < N) {
                float v = acc[i][j];
                float* cp = C + (size_t)m * ldc + n;
                if (EPI == 2) {
                    float s = v + bias[n];
                    *cp = fmaxf(s, 0.f) + log1pf(__expf(-fabsf(s)));
                } else {
                    *cp = v;
                }
            }
        }
    }
}

// ---------------- layernorm over rows of length DM=1024 -------------------
__global__ void __launch_bounds__(256)
ln_kernel(const float* __restrict__ x, const float* __restrict__ w,
          const float* __restrict__ b, float* __restrict__ y)
{
    const int row = blockIdx.x;
    const float* xr = x + (size_t)row * DM;
    float* yr = y + (size_t)row * DM;
    const int tid = threadIdx.x;

    float vals[4];
    float s = 0.f, ss = 0.f;
    #pragma unroll
    for (int i = 0; i < 4; i++) {
        float v = xr[tid + i * 256];
        vals[i] = v;
        s += v; ss += v * v;
    }
    #pragma unroll
    for (int o = 16; o > 0; o >>= 1) {
        s  += __shfl_xor_sync(0xffffffffu, s, o);
        ss += __shfl_xor_sync(0xffffffffu, ss, o);
    }
    __shared__ float sh[16], shh[16];
    int wid = tid >> 5, ln = tid & 31;
    if (ln == 0) { sh[wid] = s; shh[wid] = ss; }
    __syncthreads();
    if (wid == 0) {
        float a = (ln < 8) ? sh[ln] : 0.f;
        float c = (ln < 8) ? shh[ln] : 0.f;
        #pragma unroll
        for (int o = 4; o > 0; o >>= 1) {
            a += __shfl_xor_sync(0xffffffffu, a, o);
            c += __shfl_xor_sync(0xffffffffu, c, o);
        }
        if (ln == 0) { sh[0] = a; shh[0] = c; }
    }
    __syncthreads();
    float mean = sh[0] * (1.f / DM);
    float var  = shh[0] * (1.f / DM) - mean * mean;
    float rstd = rsqrtf(var + 1e-5f);
    #pragma unroll
    for (int i = 0; i < 4; i++) {
        int c = tid + i * 256;
        yr[c] = (vals[i] - mean) * rstd * w[c] + b[c];
    }
}

// -------- depthwise causal conv (K=4) + bias + silu -----------------------
__global__ void __launch_bounds__(256)
conv_silu_kernel(const float* __restrict__ xz, const float* __restrict__ cw,
                 const float* __restrict__ cb, float* __restrict__ xm)
{
    const int e  = blockIdx.x * 256 + threadIdx.x;
    const int t0 = blockIdx.y * 8;
    const int b  = blockIdx.z;
    const float4 w = *(const float4*)(cw + e * 4);
    const float bias = cb[e];
    const float* base = xz + (size_t)b * Lseq * (2 * Eexp) + e;

    float v[11];
    #pragma unroll
    for (int i = 0; i < 11; i++) {
        int t = t0 - 3 + i;
        v[i] = (t >= 0) ? base[(size_t)t * (2 * Eexp)] : 0.f;
    }
    #pragma unroll
    for (int j = 0; j < 8; j++) {
        float sacc = bias;
        sacc = fmaf(w.x, v[j],     sacc);
        sacc = fmaf(w.y, v[j + 1], sacc);
        sacc = fmaf(w.z, v[j + 2], sacc);
        sacc = fmaf(w.w, v[j + 3], sacc);
        float sv = sacc / (1.f + __expf(-sacc));
        xm[((size_t)b * Lseq + t0 + j) * Eexp + e] = sv;
    }
}

// ---------------- selective scan + gating ---------------------------------
__global__ void __launch_bounds__(256)
scan_kernel(const float* __restrict__ u,    const float* __restrict__ dt,
            const float* __restrict__ xdbl, const float* __restrict__ Alog,
            const float* __restrict__ Dp,   const float* __restrict__ xz,
            float* __restrict__ yg)
{
    const int tid = threadIdx.x;
    const int grp = tid >> 4;
    const int n   = tid & 15;
    const int blk = blockIdx.x;
    const int b   = blk >> 7;
    const int e   = ((blk & 127) << 4) + grp;

    const float A = -__expf(Alog[e * Nst + n]);
    const float D = Dp[e];
    float h = 0.f;
    const size_t rbase = (size_t)b * Lseq;

    float dts = dt[rbase * Eexp + e];
    float us  = u [rbase * Eexp + e];
    float Bn  = xdbl[rbase * 96 + Rrank + n];
    float Cn  = xdbl[rbase * 96 + Rrank + Nst + n];

    for (int t = 0; t < Lseq; t++) {
        float dts_c = dts, us_c = us, Bn_c = Bn, Cn_c = Cn;
        if (t + 1 < Lseq) {
            size_t r = rbase + t + 1;
            dts = dt[r * Eexp + e];
            us  = u [r * Eexp + e];
            Bn  = xdbl[r * 96 + Rrank + n];
            Cn  = xdbl[r * 96 + Rrank + Nst + n];
        }
        float dA = __expf(dts_c * A);
        h = fmaf(dA, h, (dts_c * us_c) * Bn_c);
        float p = h * Cn_c;
        p += __shfl_xor_sync(0xffffffffu, p, 1);
        p += __shfl_xor_sync(0xffffffffu, p, 2);
        p += __shfl_xor_sync(0xffffffffu, p, 4);
        p += __shfl_xor_sync(0xffffffffu, p, 8);
        if (n == 0) {
            size_t r = rbase + t;
            float zv = xz[r * (2 * Eexp) + Eexp + e];
            float yv = fmaf(us_c, D, p);
            yg[r * Eexp + e] = yv * (zv / (1.f + __expf(-zv)));
        }
    }
}

// ---------------- host driver ---------------------------------------------
#define TGEMM_SMEM (4 * TSTAGE * (int)sizeof(float))   // 73728 bytes

extern "C" void kernel_launch(void* const* d_in, const int* in_sizes, int n_in,
                              void* d_out, int out_size)
{
    const float* x        = (const float*)d_in[0];
    const float* ip_w     = (const float*)d_in[2];
    const float* ip_b     = (const float*)d_in[3];
    const float* ln_w     = (const float*)d_in[4];
    const float* ln_b     = (const float*)d_in[5];
    const float* inproj_w = (const float*)d_in[6];
    const float* conv_w   = (const float*)d_in[7];
    const float* conv_b   = (const float*)d_in[8];
    const float* xproj_w  = (const float*)d_in[9];
    const float* dtproj_w = (const float*)d_in[10];
    const float* dtproj_b = (const float*)d_in[11];
    const float* A_log    = (const float*)d_in[12];
    const float* Dp       = (const float*)d_in[13];
    const float* outproj_w= (const float*)d_in[14];
    const float* fnorm_w  = (const float*)d_in[15];
    const float* fnorm_b  = (const float*)d_in[16];
    const float* op_w     = (const float*)d_in[17];
    const float* op_b     = (const float*)d_in[18];
    float* out = (float*)d_out;

    float *h, *hn, *xz, *xm, *xdbl, *dtb, *yg;
    cudaGetSymbolAddress((void**)&h,    g_h);
    cudaGetSymbolAddress((void**)&hn,   g_hn);
    cudaGetSymbolAddress((void**)&xz,   g_xz);
    cudaGetSymbolAddress((void**)&xm,   g_xm);
    cudaGetSymbolAddress((void**)&xdbl, g_xdbl);
    cudaGetSymbolAddress((void**)&dtb,  g_dt);
    cudaGetSymbolAddress((void**)&yg,   g_yg);

    cudaFuncSetAttribute(tgemm_nt<0>, cudaFuncAttributeMaxDynamicSharedMemorySize, TGEMM_SMEM);
    cudaFuncSetAttribute(tgemm_nt<1>, cudaFuncAttributeMaxDynamicSharedMemorySize, TGEMM_SMEM);
    cudaFuncSetAttribute(tgemm_nt<3>, cudaFuncAttributeMaxDynamicSharedMemorySize, TGEMM_SMEM);

    // input projection: h = x @ ip_w^T + ip_b   (2048 x 1024 x 512)
    tgemm_nt<1><<<dim3(DM / TBN, Mrows / TBM), 256, TGEMM_SMEM>>>(
        x, DIN, ip_w, DIN, h, DM, Mrows, DM, DIN, ip_b);

    for (int l = 0; l < NLAYER; l++) {
        ln_kernel<<<Mrows, 256>>>(h, ln_w + l * DM, ln_b + l * DM, hn);

        // xz = hn @ inproj^T   (2048 x 4096 x 1024)
        tgemm_nt<0><<<dim3(2 * Eexp / TBN, Mrows / TBM), 256, TGEMM_SMEM>>>(
            hn, DM, inproj_w + (size_t)l * 2 * Eexp * DM, DM,
            xz, 2 * Eexp, Mrows, 2 * Eexp, DM, nullptr);

        conv_silu_kernel<<<dim3(Eexp / 256, Lseq / 8, Bsz), 256>>>(
            xz, conv_w + l * Eexp * Kconv, conv_b + l * Eexp, xm);

        // x_dbl = xm @ xproj^T   (2048 x 96 x 2048)
        tgemm_nt<0><<<dim3(1, Mrows / TBM), 256, TGEMM_SMEM>>>(
            xm, Eexp, xproj_w + (size_t)l * 96 * Eexp, Eexp,
            xdbl, 96, Mrows, 96, Eexp, nullptr);

        // dt = softplus(x_dbl[:, :R] @ dtproj^T + dtproj_b) -- fp32 for accuracy
        sgemm_nt<2><<<dim3(Eexp / BN, Mrows / BM), 256>>>(
            xdbl, 96, dtproj_w + (size_t)l * Eexp * Rrank, Rrank,
            dtb, Eexp, Mrows, Eexp, Rrank, dtproj_b + l * Eexp);

        scan_kernel<<<256, 256>>>(
            xm, dtb, xdbl, A_log + l * Eexp * Nst, Dp + l * Eexp, xz, yg);

        // h += yg @ outproj^T   (2048 x 1024 x 2048)
        tgemm_nt<3><<<dim3(DM / TBN, Mrows / TBM), 256, TGEMM_SMEM>>>(
            yg, Eexp, outproj_w + (size_t)l * DM * Eexp, Eexp,
            h, DM, Mrows, DM, Eexp, nullptr);
    }

    ln_kernel<<<Mrows, 256>>>(h, fnorm_w, fnorm_b, hn);
    tgemm_nt<1><<<dim3(DIN / TBN, Mrows / TBM), 256, TGEMM_SMEM>>>(
        hn, DM, op_w, DM, out, DIN, Mrows, DIN, DM, op_b);
}

// round 7
// speedup vs baseline: 2.2702x; 1.2033x over previous
#include <cuda_runtime.h>
#include <cuda_fp16.h>
#include <cuda_bf16.h>
#include <cstdint>

// Problem constants
#define Bsz 2
#define Lseq 1024
#define DIN 512
#define DM 1024
#define NLAYER 4
#define Eexp 2048
#define Nst 16
#define Rrank 64
#define Kconv 4
#define Mrows (Bsz*Lseq)   // 2048

// ---------------- scratch (device globals; no allocation allowed) ----------
__device__ float g_h   [Mrows*DM];
__device__ float g_xz  [Mrows*2*Eexp];
__device__ float g_xm  [Mrows*Eexp];
__device__ float g_xdbl[Mrows*96];
__device__ float g_dt  [Mrows*Eexp];
__device__ __half g_hnh[Mrows*DM];        // LN output (fp16 for GEMM A)
__device__ __half g_ygh[Mrows*Eexp];      // gated scan output (fp16)
__device__ __half g_xh [Mrows*DIN];       // converted input x
// converted weights: ip | inproj | outproj | op
#define WOFF_IP      0
#define WOFF_INPROJ  (WOFF_IP + DM*DIN)                       // 524288
#define WOFF_OUTPROJ (WOFF_INPROJ + NLAYER*2*Eexp*DM)         // 17301504
#define WOFF_OP      (WOFF_OUTPROJ + NLAYER*DM*Eexp)          // 25690112
#define WTOTAL       (WOFF_OP + DIN*DM)                       // 26214400
__device__ __half g_wh[WTOTAL];

// ---------------- small PTX helpers ----------------------------------------
__device__ __forceinline__ uint32_t smem_u32(const void* p) {
    return (uint32_t)__cvta_generic_to_shared(p);
}
__device__ __forceinline__ void cp_async16(uint32_t dst, const void* src) {
    asm volatile("cp.async.cg.shared.global [%0], [%1], 16;\n"
                 :: "r"(dst), "l"(src));
}
__device__ __forceinline__ void cp_commit() {
    asm volatile("cp.async.commit_group;\n");
}
template<int NPend>
__device__ __forceinline__ void cp_wait() {
    asm volatile("cp.async.wait_group %0;\n" :: "n"(NPend));
}
__device__ __forceinline__ void ldsm_x4(uint32_t& r0, uint32_t& r1,
                                        uint32_t& r2, uint32_t& r3, uint32_t addr) {
    asm volatile("ldmatrix.sync.aligned.m8n8.x4.shared.b16 {%0,%1,%2,%3}, [%4];"
                 : "=r"(r0), "=r"(r1), "=r"(r2), "=r"(r3) : "r"(addr));
}
__device__ __forceinline__ void mma_f16(float* d, const uint32_t* a, const uint32_t* b) {
    asm volatile(
        "mma.sync.aligned.m16n8k16.row.col.f32.f16.f16.f32 "
        "{%0,%1,%2,%3}, {%4,%5,%6,%7}, {%8,%9}, {%0,%1,%2,%3};\n"
        : "+f"(d[0]), "+f"(d[1]), "+f"(d[2]), "+f"(d[3])
        : "r"(a[0]), "r"(a[1]), "r"(a[2]), "r"(a[3]), "r"(b[0]), "r"(b[1]));
}
__device__ __forceinline__ void mma_tf32(float* d, const uint32_t* a, const uint32_t* b) {
    asm volatile(
        "mma.sync.aligned.m16n8k8.row.col.f32.tf32.tf32.f32 "
        "{%0,%1,%2,%3}, {%4,%5,%6,%7}, {%8,%9}, {%0,%1,%2,%3};\n"
        : "+f"(d[0]), "+f"(d[1]), "+f"(d[2]), "+f"(d[3])
        : "r"(a[0]), "r"(a[1]), "r"(a[2]), "r"(a[3]), "r"(b[0]), "r"(b[1]));
}

// =================== fp16 tensor-core NT GEMM ==============================
// C[m,n] = sum_k A[m,k]*W[n,k]; A [M,K] half row-major, W [N,K] half row-major
// M,N multiples of 128; K multiple of 32.  EPI: 0 store, 1 +bias, 3 C += acc
#define HRS 40                              // smem row stride in halfs (80 B)
#define HSTAGE_H (128*HRS)                  // halfs per operand per stage
#define HSTAGE_BYTES (HSTAGE_H*2)           // 10240
#define HSTAGES 3
#define HSMEM_TOTAL (2*HSTAGES*HSTAGE_BYTES)  // 61440

template<int EPI>
__global__ void __launch_bounds__(256, 2)
hgemm_nt(const __half* __restrict__ A, int lda,
         const __half* __restrict__ W, int ldw,
         float* __restrict__ C, int ldc,
         int K, const float* __restrict__ bias)
{
    extern __shared__ char smem[];
    __half* As = (__half*)smem;
    __half* Ws = (__half*)(smem + HSTAGES * HSTAGE_BYTES);

    const int tid  = threadIdx.x;
    const int warp = tid >> 5, lane = tid & 31;
    const int bm   = blockIdx.y * 128;
    const int bn   = blockIdx.x * 128;
    const int wm   = warp & 3;          // 0..3 -> 32-row band
    const int wn   = warp >> 2;         // 0..1 -> 64-col band
    const int gid  = lane >> 2, tig = lane & 3;

    float acc[2][8][4];
    #pragma unroll
    for (int i = 0; i < 2; i++)
        #pragma unroll
        for (int j = 0; j < 8; j++)
            #pragma unroll
            for (int q = 0; q < 4; q++) acc[i][j][q] = 0.f;

    // loaders: tile = 128 rows x 32 halfs = 512 x 16B granules, 2/thread
    auto ldA = [&](int s, int kt) {
        #pragma unroll
        for (int t = 0; t < 2; t++) {
            int idx = tid + t * 256;
            int r = idx >> 2, g = idx & 3;
            cp_async16(smem_u32(As + s * HSTAGE_H + r * HRS + g * 8),
                       A + (size_t)(bm + r) * lda + kt * 32 + g * 8);
        }
    };
    auto ldW = [&](int s, int kt) {
        #pragma unroll
        for (int t = 0; t < 2; t++) {
            int idx = tid + t * 256;
            int r = idx >> 2, g = idx & 3;
            cp_async16(smem_u32(Ws + s * HSTAGE_H + r * HRS + g * 8),
                       W + (size_t)(bn + r) * ldw + kt * 32 + g * 8);
        }
    };

    const int nk = K / 32;
    ldA(0, 0); ldW(0, 0); cp_commit();
    ldA(1, 1); ldW(1, 1); cp_commit();

    // ldmatrix base offsets (within a stage)
    const int arow = wm * 32 + (lane & 15);
    const int acol = (lane >> 4) << 3;                        // 0 or 8
    const int brow = wn * 64 + (lane & 7) + ((lane & 16) >> 1); // +8 for hi half
    const int bcol = lane & 8;

    for (int it = 0; it < nk; it++) {
        const int s = it % HSTAGES;
        if (it == nk - 1) cp_wait<0>(); else cp_wait<1>();
        __syncthreads();

        const __half* Asb = As + s * HSTAGE_H;
        const __half* Wsb = Ws + s * HSTAGE_H;

        #pragma unroll
        for (int kk = 0; kk < 32; kk += 16) {
            uint32_t af[2][4];
            #pragma unroll
            for (int mt = 0; mt < 2; mt++)
                ldsm_x4(af[mt][0], af[mt][1], af[mt][2], af[mt][3],
                        smem_u32(Asb + (arow + mt * 16) * HRS + kk + acol));
            uint32_t bf[8][2];
            #pragma unroll
            for (int ntp = 0; ntp < 4; ntp++)
                ldsm_x4(bf[ntp * 2][0], bf[ntp * 2][1],
                        bf[ntp * 2 + 1][0], bf[ntp * 2 + 1][1],
                        smem_u32(Wsb + (brow + ntp * 16) * HRS + kk + bcol));
            #pragma unroll
            for (int mt = 0; mt < 2; mt++)
                #pragma unroll
                for (int nt = 0; nt < 8; nt++)
                    mma_f16(acc[mt][nt], af[mt], bf[nt]);
        }

        if (it + 2 < nk) {
            const int s2 = (it + 2) % HSTAGES;
            ldA(s2, it + 2); ldW(s2, it + 2); cp_commit();
        }
    }

    // epilogue (c-frag: rows gid, gid+8; cols tig*2, tig*2+1)
    #pragma unroll
    for (int mt = 0; mt < 2; mt++) {
        int r0 = bm + wm * 32 + mt * 16 + gid;
        #pragma unroll
        for (int nt = 0; nt < 8; nt++) {
            int n0 = bn + wn * 64 + nt * 8 + tig * 2;
            #pragma unroll
            for (int hh = 0; hh < 2; hh++) {
                float* cp = C + (size_t)(r0 + hh * 8) * ldc + n0;
                float2 v = make_float2(acc[mt][nt][hh * 2], acc[mt][nt][hh * 2 + 1]);
                if (EPI == 1) {
                    v.x += bias[n0]; v.y += bias[n0 + 1];
                } else if (EPI == 3) {
                    float2 o = *(float2*)cp;
                    v.x += o.x; v.y += o.y;
                }
                *(float2*)cp = v;
            }
        }
    }
}

// =================== tf32 tensor-core NT GEMM (xproj only, N=96) ===========
#define TBM 128
#define TBN 128
#define TBK 32
#define TROW 36
#define TSTAGE (TBM*TROW)
#define TGEMM_SMEM (4 * TSTAGE * (int)sizeof(float))

__device__ __forceinline__ void cp_async16g(uint32_t dst, const void* src, int src_bytes) {
    asm volatile("cp.async.cg.shared.global [%0], [%1], 16, %2;\n"
                 :: "r"(dst), "l"(src), "r"(src_bytes));
}

__global__ void __launch_bounds__(256, 2)
tgemm_nt(const float* __restrict__ A, int lda,
         const float* __restrict__ W, int ldw,
         float* __restrict__ C, int ldc,
         int M, int N, int K)
{
    extern __shared__ float sm[];
    float* As = sm;
    float* Ws = sm + 2 * TSTAGE;

    const int tid  = threadIdx.x;
    const int bm   = blockIdx.y * TBM;
    const int bn   = blockIdx.x * TBN;
    const int warp = tid >> 5, lane = tid & 31;
    const int wm   = warp & 3;
    const int wn   = warp >> 2;
    const int gid  = lane >> 2, tig = lane & 3;

    float acc[2][8][4];
    #pragma unroll
    for (int i = 0; i < 2; i++)
        #pragma unroll
        for (int j = 0; j < 8; j++)
            #pragma unroll
            for (int q = 0; q < 4; q++) acc[i][j][q] = 0.f;

    auto ldA = [&](int stage, int k0) {
        #pragma unroll
        for (int t = 0; t < 4; t++) {
            int idx = tid + t * 256;
            int r = idx >> 3, kc = (idx & 7) * 4;
            cp_async16g(smem_u32(As + stage * TSTAGE + r * TROW + kc),
                        A + (size_t)(bm + r) * lda + k0 + kc, 16);
        }
    };
    auto ldW = [&](int stage, int k0) {
        #pragma unroll
        for (int t = 0; t < 4; t++) {
            int idx = tid + t * 256;
            int r = idx >> 3, kc = (idx & 7) * 4;
            int n = bn + r;
            int ok = (n < N);
            cp_async16g(smem_u32(Ws + stage * TSTAGE + r * TROW + kc),
                        W + (size_t)(ok ? n : 0) * ldw + k0 + kc, ok ? 16 : 0);
        }
    };

    const int nk = K / TBK;
    ldA(0, 0); ldW(0, 0); cp_commit();

    for (int it = 0; it < nk; it++) {
        int stage = it & 1;
        if (it + 1 < nk) {
            ldA(stage ^ 1, (it + 1) * TBK);
            ldW(stage ^ 1, (it + 1) * TBK);
            cp_commit();
            cp_wait<1>();
        } else {
            cp_wait<0>();
        }
        __syncthreads();

        const uint32_t* Asu = (const uint32_t*)(As + stage * TSTAGE);
        const uint32_t* Wsu = (const uint32_t*)(Ws + stage * TSTAGE);

        #pragma unroll
        for (int kk = 0; kk < TBK; kk += 8) {
            uint32_t af[2][4];
            #pragma unroll
            for (int mt = 0; mt < 2; mt++) {
                int r = wm * 32 + mt * 16 + gid;
                const uint32_t* ap = Asu + r * TROW + kk + tig;
                af[mt][0] = ap[0];
                af[mt][1] = ap[8 * TROW];
                af[mt][2] = ap[4];
                af[mt][3] = ap[8 * TROW + 4];
            }
            uint32_t bfr[8][2];
            #pragma unroll
            for (int nt = 0; nt < 8; nt++) {
                int n = wn * 64 + nt * 8 + gid;
                const uint32_t* bp = Wsu + n * TROW + kk + tig;
                bfr[nt][0] = bp[0];
                bfr[nt][1] = bp[4];
            }
            #pragma unroll
            for (int mt = 0; mt < 2; mt++)
                #pragma unroll
                for (int nt = 0; nt < 8; nt++)
                    mma_tf32(acc[mt][nt], af[mt], bfr[nt]);
        }
        __syncthreads();
    }

    #pragma unroll
    for (int mt = 0; mt < 2; mt++) {
        int r0 = bm + wm * 32 + mt * 16 + gid;
        #pragma unroll
        for (int nt = 0; nt < 8; nt++) {
            int col = bn + wn * 64 + nt * 8 + tig * 2;
            #pragma unroll
            for (int h = 0; h < 2; h++) {
                int m = r0 + h * 8;
                #pragma unroll
                for (int q = 0; q < 2; q++) {
                    int n = col + q;
                    if (n < N) C[(size_t)m * ldc + n] = acc[mt][nt][h * 2 + q];
                }
            }
        }
    }
}

// =================== fp32 SIMT GEMM (dtproj, accuracy-critical) ============
#define BM 128
#define BN 128
#define BKs 16
#define TM 8
#define TN 8

__global__ void __launch_bounds__(256)
sgemm_softplus(const float* __restrict__ A, int lda,
               const float* __restrict__ W, int ldw,
               float* __restrict__ C, int ldc,
               int K, const float* __restrict__ bias)
{
    __shared__ float As[BKs][BM];
    __shared__ float Ws[BKs][BN];

    const int tid = threadIdx.x;
    const int bm = blockIdx.y * BM;
    const int bn = blockIdx.x * BN;
    const int tx = tid & 15;
    const int ty = tid >> 4;
    const int lr = tid >> 2;
    const int lc = (tid & 3) * 4;

    float acc[TM][TN];
    #pragma unroll
    for (int i = 0; i < TM; i++)
        #pragma unroll
        for (int j = 0; j < TN; j++) acc[i][j] = 0.f;

    for (int k0 = 0; k0 < K; k0 += BKs) {
        #pragma unroll
        for (int h = 0; h < 2; h++) {
            int r = lr + h * 64;
            float4 v = *(const float4*)(A + (size_t)(bm + r) * lda + k0 + lc);
            As[lc + 0][r] = v.x; As[lc + 1][r] = v.y;
            As[lc + 2][r] = v.z; As[lc + 3][r] = v.w;
        }
        #pragma unroll
        for (int h = 0; h < 2; h++) {
            int r = lr + h * 64;
            float4 v = *(const float4*)(W + (size_t)(bn + r) * ldw + k0 + lc);
            Ws[lc + 0][r] = v.x; Ws[lc + 1][r] = v.y;
            Ws[lc + 2][r] = v.z; Ws[lc + 3][r] = v.w;
        }
        __syncthreads();

        #pragma unroll
        for (int k = 0; k < BKs; k++) {
            float a[TM], b[TN];
            #pragma unroll
            for (int i = 0; i < TM; i++) a[i] = As[k][ty * TM + i];
            #pragma unroll
            for (int j = 0; j < TN; j++) b[j] = Ws[k][tx * TN + j];
            #pragma unroll
            for (int i = 0; i < TM; i++)
                #pragma unroll
                for (int j = 0; j < TN; j++)
                    acc[i][j] = fmaf(a[i], b[j], acc[i][j]);
        }
        __syncthreads();
    }

    #pragma unroll
    for (int i = 0; i < TM; i++) {
        int m = bm + ty * TM + i;
        #pragma unroll
        for (int j = 0; j < TN; j++) {
            int n = bn + tx * TN + j;
            float s = acc[i][j] + bias[n];
            C[(size_t)m * ldc + n] = fmaxf(s, 0.f) + log1pf(__expf(-fabsf(s)));
        }
    }
}

// ---------------- float -> half conversion (grid-stride by 4) --------------
__global__ void __launch_bounds__(256)
cvt_f2h(const float* __restrict__ s, __half* __restrict__ d, int n)
{
    int i = (blockIdx.x * 256 + threadIdx.x) * 4;
    if (i < n) {
        float4 v = *(const float4*)(s + i);
        __half2* p = (__half2*)(d + i);
        p[0] = __floats2half2_rn(v.x, v.y);
        p[1] = __floats2half2_rn(v.z, v.w);
    }
}

// ---------------- layernorm over rows of length DM=1024, fp16 out ---------
__global__ void __launch_bounds__(256)
ln_kernel(const float* __restrict__ x, const float* __restrict__ w,
          const float* __restrict__ b, __half* __restrict__ y)
{
    const int row = blockIdx.x;
    const float* xr = x + (size_t)row * DM;
    __half* yr = y + (size_t)row * DM;
    const int tid = threadIdx.x;

    float vals[4];
    float s = 0.f, ss = 0.f;
    #pragma unroll
    for (int i = 0; i < 4; i++) {
        float v = xr[tid + i * 256];
        vals[i] = v;
        s += v; ss += v * v;
    }
    #pragma unroll
    for (int o = 16; o > 0; o >>= 1) {
        s  += __shfl_xor_sync(0xffffffffu, s, o);
        ss += __shfl_xor_sync(0xffffffffu, ss, o);
    }
    __shared__ float sh[16], shh[16];
    int wid = tid >> 5, ln = tid & 31;
    if (ln == 0) { sh[wid] = s; shh[wid] = ss; }
    __syncthreads();
    if (wid == 0) {
        float a = (ln < 8) ? sh[ln] : 0.f;
        float c = (ln < 8) ? shh[ln] : 0.f;
        #pragma unroll
        for (int o = 4; o > 0; o >>= 1) {
            a += __shfl_xor_sync(0xffffffffu, a, o);
            c += __shfl_xor_sync(0xffffffffu, c, o);
        }
        if (ln == 0) { sh[0] = a; shh[0] = c; }
    }
    __syncthreads();
    float mean = sh[0] * (1.f / DM);
    float var  = shh[0] * (1.f / DM) - mean * mean;
    float rstd = rsqrtf(var + 1e-5f);
    #pragma unroll
    for (int i = 0; i < 4; i++) {
        int c = tid + i * 256;
        yr[c] = __float2half((vals[i] - mean) * rstd * w[c] + b[c]);
    }
}

// -------- depthwise causal conv (K=4) + bias + silu -----------------------
__global__ void __launch_bounds__(256)
conv_silu_kernel(const float* __restrict__ xz, const float* __restrict__ cw,
                 const float* __restrict__ cb, float* __restrict__ xm)
{
    const int e  = blockIdx.x * 256 + threadIdx.x;
    const int t0 = blockIdx.y * 8;
    const int b  = blockIdx.z;
    const float4 w = *(const float4*)(cw + e * 4);
    const float bias = cb[e];
    const float* base = xz + (size_t)b * Lseq * (2 * Eexp) + e;

    float v[11];
    #pragma unroll
    for (int i = 0; i < 11; i++) {
        int t = t0 - 3 + i;
        v[i] = (t >= 0) ? base[(size_t)t * (2 * Eexp)] : 0.f;
    }
    #pragma unroll
    for (int j = 0; j < 8; j++) {
        float sacc = bias;
        sacc = fmaf(w.x, v[j],     sacc);
        sacc = fmaf(w.y, v[j + 1], sacc);
        sacc = fmaf(w.z, v[j + 2], sacc);
        sacc = fmaf(w.w, v[j + 3], sacc);
        float sv = sacc / (1.f + __expf(-sacc));
        xm[((size_t)b * Lseq + t0 + j) * Eexp + e] = sv;
    }
}

// ---------------- selective scan + gating (fp16 output) -------------------
__global__ void __launch_bounds__(256)
scan_kernel(const float* __restrict__ u,    const float* __restrict__ dt,
            const float* __restrict__ xdbl, const float* __restrict__ Alog,
            const float* __restrict__ Dp,   const float* __restrict__ xz,
            __half* __restrict__ yg)
{
    const int tid = threadIdx.x;
    const int grp = tid >> 4;
    const int n   = tid & 15;
    const int blk = blockIdx.x;
    const int b   = blk >> 7;
    const int e   = ((blk & 127) << 4) + grp;

    const float A = -__expf(Alog[e * Nst + n]);
    const float D = Dp[e];
    float h = 0.f;
    const size_t rbase = (size_t)b * Lseq;

    float dts = dt[rbase * Eexp + e];
    float us  = u [rbase * Eexp + e];
    float Bn  = xdbl[rbase * 96 + Rrank + n];
    float Cn  = xdbl[rbase * 96 + Rrank + Nst + n];

    for (int t = 0; t < Lseq; t++) {
        float dts_c = dts, us_c = us, Bn_c = Bn, Cn_c = Cn;
        if (t + 1 < Lseq) {
            size_t r = rbase + t + 1;
            dts = dt[r * Eexp + e];
            us  = u [r * Eexp + e];
            Bn  = xdbl[r * 96 + Rrank + n];
            Cn  = xdbl[r * 96 + Rrank + Nst + n];
        }
        float dA = __expf(dts_c * A);
        h = fmaf(dA, h, (dts_c * us_c) * Bn_c);
        float p = h * Cn_c;
        p += __shfl_xor_sync(0xffffffffu, p, 1);
        p += __shfl_xor_sync(0xffffffffu, p, 2);
        p += __shfl_xor_sync(0xffffffffu, p, 4);
        p += __shfl_xor_sync(0xffffffffu, p, 8);
        if (n == 0) {
            size_t r = rbase + t;
            float zv = xz[r * (2 * Eexp) + Eexp + e];
            float yv = fmaf(us_c, D, p);
            yg[r * Eexp + e] = __float2half(yv * (zv / (1.f + __expf(-zv))));
        }
    }
}

// ---------------- host driver ---------------------------------------------
extern "C" void kernel_launch(void* const* d_in, const int* in_sizes, int n_in,
                              void* d_out, int out_size)
{
    const float* x        = (const float*)d_in[0];
    const float* ip_w     = (const float*)d_in[2];
    const float* ip_b     = (const float*)d_in[3];
    const float* ln_w     = (const float*)d_in[4];
    const float* ln_b     = (const float*)d_in[5];
    const float* inproj_w = (const float*)d_in[6];
    const float* conv_w   = (const float*)d_in[7];
    const float* conv_b   = (const float*)d_in[8];
    const float* xproj_w  = (const float*)d_in[9];
    const float* dtproj_w = (const float*)d_in[10];
    const float* dtproj_b = (const float*)d_in[11];
    const float* A_log    = (const float*)d_in[12];
    const float* Dp       = (const float*)d_in[13];
    const float* outproj_w= (const float*)d_in[14];
    const float* fnorm_w  = (const float*)d_in[15];
    const float* fnorm_b  = (const float*)d_in[16];
    const float* op_w     = (const float*)d_in[17];
    const float* op_b     = (const float*)d_in[18];
    float* out = (float*)d_out;

    float *h, *xz, *xm, *xdbl, *dtb;
    __half *hnh, *ygh, *xh, *wh;
    cudaGetSymbolAddress((void**)&h,    g_h);
    cudaGetSymbolAddress((void**)&xz,   g_xz);
    cudaGetSymbolAddress((void**)&xm,   g_xm);
    cudaGetSymbolAddress((void**)&xdbl, g_xdbl);
    cudaGetSymbolAddress((void**)&dtb,  g_dt);
    cudaGetSymbolAddress((void**)&hnh,  g_hnh);
    cudaGetSymbolAddress((void**)&ygh,  g_ygh);
    cudaGetSymbolAddress((void**)&xh,   g_xh);
    cudaGetSymbolAddress((void**)&wh,   g_wh);

    cudaFuncSetAttribute(hgemm_nt<0>, cudaFuncAttributeMaxDynamicSharedMemorySize, HSMEM_TOTAL);
    cudaFuncSetAttribute(hgemm_nt<1>, cudaFuncAttributeMaxDynamicSharedMemorySize, HSMEM_TOTAL);
    cudaFuncSetAttribute(hgemm_nt<3>, cudaFuncAttributeMaxDynamicSharedMemorySize, HSMEM_TOTAL);
    cudaFuncSetAttribute(tgemm_nt, cudaFuncAttributeMaxDynamicSharedMemorySize, TGEMM_SMEM);

    // ---- fp32 -> fp16 conversions (weights + input) ----
    auto cvt = [&](const float* s, __half* d, int n) {
        cvt_f2h<<<(n / 4 + 255) / 256, 256>>>(s, d, n);
    };
    cvt(x,         xh,               Mrows * DIN);
    cvt(ip_w,      wh + WOFF_IP,     DM * DIN);
    cvt(inproj_w,  wh + WOFF_INPROJ, NLAYER * 2 * Eexp * DM);
    cvt(outproj_w, wh + WOFF_OUTPROJ,NLAYER * DM * Eexp);
    cvt(op_w,      wh + WOFF_OP,     DIN * DM);

    // input projection: h = x @ ip_w^T + ip_b   (2048 x 1024 x 512)
    hgemm_nt<1><<<dim3(DM / 128, Mrows / 128), 256, HSMEM_TOTAL>>>(
        xh, DIN, wh + WOFF_IP, DIN, h, DM, DIN, ip_b);

    for (int l = 0; l < NLAYER; l++) {
        ln_kernel<<<Mrows, 256>>>(h, ln_w + l * DM, ln_b + l * DM, hnh);

        // xz = hn @ inproj^T   (2048 x 4096 x 1024)
        hgemm_nt<0><<<dim3(2 * Eexp / 128, Mrows / 128), 256, HSMEM_TOTAL>>>(
            hnh, DM, wh + WOFF_INPROJ + (size_t)l * 2 * Eexp * DM, DM,
            xz, 2 * Eexp, DM, nullptr);

        conv_silu_kernel<<<dim3(Eexp / 256, Lseq / 8, Bsz), 256>>>(
            xz, conv_w + l * Eexp * Kconv, conv_b + l * Eexp, xm);

        // x_dbl = xm @ xproj^T   (2048 x 96 x 2048) -- tf32 (precision path)
        tgemm_nt<<<dim3(1, Mrows / TBM), 256, TGEMM_SMEM>>>(
            xm, Eexp, xproj_w + (size_t)l * 96 * Eexp, Eexp,
            xdbl, 96, Mrows, 96, Eexp);

        // dt = softplus(x_dbl[:, :R] @ dtproj^T + dtproj_b) -- fp32
        sgemm_softplus<<<dim3(Eexp / BN, Mrows / BM), 256>>>(
            xdbl, 96, dtproj_w + (size_t)l * Eexp * Rrank, Rrank,
            dtb, Eexp, Rrank, dtproj_b + l * Eexp);

        scan_kernel<<<256, 256>>>(
            xm, dtb, xdbl, A_log + l * Eexp * Nst, Dp + l * Eexp, xz, ygh);

        // h += yg @ outproj^T   (2048 x 1024 x 2048)
        hgemm_nt<3><<<dim3(DM / 128, Mrows / 128), 256, HSMEM_TOTAL>>>(
            ygh, Eexp, wh + WOFF_OUTPROJ + (size_t)l * DM * Eexp, Eexp,
            h, DM, Eexp, nullptr);
    }

    ln_kernel<<<Mrows, 256>>>(h, fnorm_w, fnorm_b, hnh);
    hgemm_nt<1><<<dim3(DIN / 128, Mrows / 128), 256, HSMEM_TOTAL>>>(
        hnh, DM, wh + WOFF_OP, DM, out, DIN, DM, op_b);
}